// round 1
// baseline (speedup 1.0000x reference)
#include <cuda_runtime.h>
#include <math.h>

#define NN 30000
#define NE 300000
#define HH 128
#define H3 384
#define RR 200
#define RRELU_SLOPE 0.22916666666666666f

// ---------------- scratch (__device__ globals: alloc-free) ----------------
__device__ unsigned char g_mask[(size_t)RR * NN];      // 6 MB
__device__ float g_deg[NN];
__device__ float g_rel[RR * HH];
__device__ float g_agg[(size_t)NN * HH];               // 15.4 MB
__device__ float g_nf [(size_t)NN * HH];               // layer-0 node output
__device__ float g_ef [(size_t)NE * HH];               // 154 MB, layer-0 edge output
__device__ float g_ein[(size_t)NE * HH];               // e_in, then reused as e_msg
__device__ float g_gi [(size_t)NE * H3];               // 461 MB
__device__ float g_gh [(size_t)NE * H3];               // 461 MB

// ---------------- zero kernels ----------------
__global__ void k_zero_mask_deg() {
    size_t i = (size_t)blockIdx.x * blockDim.x + threadIdx.x;
    const size_t W = (size_t)RR * NN / 4;  // 1.5M words
    if (i < W) ((unsigned int*)g_mask)[i] = 0u;
    if (i < NN) g_deg[i] = 0.0f;
}

__global__ void k_zero_agg() {
    size_t i = (size_t)blockIdx.x * blockDim.x + threadIdx.x;
    if (i < (size_t)NN * HH) g_agg[i] = 0.0f;
}

// ---------------- graph-structure build (once) ----------------
__global__ void k_build(const int* __restrict__ src, const int* __restrict__ dst,
                        const int* __restrict__ et) {
    int e = blockIdx.x * blockDim.x + threadIdx.x;
    if (e >= NE) return;
    int r = et[e];
    g_mask[(size_t)r * NN + src[e]] = 1;
    g_mask[(size_t)r * NN + dst[e]] = 1;
    atomicAdd(&g_deg[dst[e]], 1.0f);
}

// ---------------- rel_emb: masked mean of node feats per relation ----------
__global__ __launch_bounds__(256) void k_rel(const float* __restrict__ nf) {
    int r = blockIdx.x;
    int warp = threadIdx.x >> 5, lane = threadIdx.x & 31;
    const unsigned char* mrow = g_mask + (size_t)r * NN;
    float a0 = 0.f, a1 = 0.f, a2 = 0.f, a3 = 0.f;
    int cnt = 0;
    for (int base = warp * 32; base < NN; base += 256) {
        int n = base + lane;
        bool set = (n < NN) && mrow[n];
        unsigned ball = __ballot_sync(0xffffffffu, set);
        cnt += (int)set;
        while (ball) {
            int b = __ffs(ball) - 1;
            ball &= ball - 1;
            const float* row = nf + (size_t)(base + b) * HH;
            a0 += row[lane]; a1 += row[lane + 32];
            a2 += row[lane + 64]; a3 += row[lane + 96];
        }
    }
    __shared__ float ss[8][128];
    __shared__ int sc[8];
    #pragma unroll
    for (int off = 16; off; off >>= 1) cnt += __shfl_xor_sync(0xffffffffu, cnt, off);
    if (lane == 0) sc[warp] = cnt;
    ss[warp][lane] = a0; ss[warp][lane + 32] = a1;
    ss[warp][lane + 64] = a2; ss[warp][lane + 96] = a3;
    __syncthreads();
    if (threadIdx.x < 128) {
        float s = 0.f; int c = 0;
        #pragma unroll
        for (int w = 0; w < 8; w++) { s += ss[w][threadIdx.x]; c += sc[w]; }
        g_rel[r * HH + threadIdx.x] = (c > 0) ? s / (float)c : 0.0f;
    }
}

// ---------------- generic fused gather-GEMM --------------------------------
// C[M,Nout] = gatherX[M,K] @ W[Nout,K]^T + bias
// X row m = concat of K/128 segments; segment j row pointer is rowp[m][j].
// mode 0: out[m*Nout+n] = v
// mode 1: atomicAdd(g_agg[dst[m]*H + n], v)              (msg aggregation)
// mode 2: p = v + g_agg[m*H+n]/max(deg,1); out = rrelu(p) (node update)
__global__ __launch_bounds__(256) void k_gemm(
    int M, int K, int Nout,
    const float* __restrict__ s0, const int* __restrict__ i0,
    const float* __restrict__ s1, const int* __restrict__ i1,
    const float* __restrict__ s2, const int* __restrict__ i2,
    const float* __restrict__ W, const float* __restrict__ bias,
    float* __restrict__ out, int mode, const int* __restrict__ dstIdx)
{
    __shared__ float As[16][65];
    __shared__ float Bs[16][65];
    __shared__ const float* rowp[64][3];

    int tid = threadIdx.x;
    int tx = tid & 15, ty = tid >> 4;
    int m0 = blockIdx.x * 64, n0 = blockIdx.y * 64;

    if (tid < 64) {
        int e = m0 + tid;
        if (e > M - 1) e = M - 1;  // clamp for safe loads; stores guarded
        rowp[tid][0] = s0 + (size_t)(i0 ? i0[e] : e) * HH;
        rowp[tid][1] = s1 ? (s1 + (size_t)(i1 ? i1[e] : e) * HH) : s0;
        rowp[tid][2] = s2 ? (s2 + (size_t)(i2 ? i2[e] : e) * HH) : s0;
    }
    __syncthreads();

    float acc[4][4] = {};
    for (int kt = 0; kt < K; kt += 16) {
        int kg = kt + tx;
        int seg = kg >> 7, off = kg & 127;
        #pragma unroll
        for (int i = 0; i < 4; i++) {
            int m = ty + 16 * i;
            As[tx][m] = rowp[m][seg][off];
            Bs[tx][m] = W[(size_t)(n0 + m) * K + kg];
        }
        __syncthreads();
        #pragma unroll
        for (int k = 0; k < 16; k++) {
            float a0 = As[k][ty * 4 + 0], a1 = As[k][ty * 4 + 1];
            float a2 = As[k][ty * 4 + 2], a3 = As[k][ty * 4 + 3];
            float b0 = Bs[k][tx * 4 + 0], b1 = Bs[k][tx * 4 + 1];
            float b2 = Bs[k][tx * 4 + 2], b3 = Bs[k][tx * 4 + 3];
            acc[0][0] += a0 * b0; acc[0][1] += a0 * b1; acc[0][2] += a0 * b2; acc[0][3] += a0 * b3;
            acc[1][0] += a1 * b0; acc[1][1] += a1 * b1; acc[1][2] += a1 * b2; acc[1][3] += a1 * b3;
            acc[2][0] += a2 * b0; acc[2][1] += a2 * b1; acc[2][2] += a2 * b2; acc[2][3] += a2 * b3;
            acc[3][0] += a3 * b0; acc[3][1] += a3 * b1; acc[3][2] += a3 * b2; acc[3][3] += a3 * b3;
        }
        __syncthreads();
    }

    #pragma unroll
    for (int i = 0; i < 4; i++) {
        int mm = m0 + ty * 4 + i;
        if (mm >= M) continue;
        #pragma unroll
        for (int j = 0; j < 4; j++) {
            int nn = n0 + tx * 4 + j;
            float v = acc[i][j] + bias[nn];
            if (mode == 0) {
                out[(size_t)mm * Nout + nn] = v;
            } else if (mode == 1) {
                atomicAdd(&g_agg[(size_t)dstIdx[mm] * HH + nn], v);
            } else {
                float a = g_agg[(size_t)mm * HH + nn] / fmaxf(g_deg[mm], 1.0f);
                float p = v + a;
                out[(size_t)mm * HH + nn] = (p >= 0.0f) ? p : RRELU_SLOPE * p;
            }
        }
    }
}

// ---------------- GRU elementwise combine ----------------------------------
// out = (1-z)*n + z*h   with gi (from g_gi), gh (from g_gh), h = ef_in
__global__ void k_gru(const float* __restrict__ ef_in, float* __restrict__ out) {
    size_t idx = (size_t)blockIdx.x * blockDim.x + threadIdx.x;
    if (idx >= (size_t)NE * HH) return;
    size_t e = idx >> 7;
    int h = (int)(idx & 127);
    const float* gi = g_gi + e * H3;
    const float* gh = g_gh + e * H3;
    float r = 1.0f / (1.0f + expf(-(gi[h] + gh[h])));
    float z = 1.0f / (1.0f + expf(-(gi[HH + h] + gh[HH + h])));
    float n = tanhf(gi[2 * HH + h] + r * gh[2 * HH + h]);
    float hv = ef_in[idx];
    out[idx] = (1.0f - z) * n + z * hv;
}

// ---------------- launch ----------------------------------------------------
extern "C" void kernel_launch(void* const* d_in, const int* in_sizes, int n_in,
                              void* d_out, int out_size) {
    (void)in_sizes; (void)n_in; (void)out_size;
    const float* nf0 = (const float*)d_in[0];
    const float* ef0 = (const float*)d_in[1];
    const int* src = (const int*)d_in[2];
    const int* dst = (const int*)d_in[3];
    const int* et  = (const int*)d_in[4];
    const float* W1  = (const float*)d_in[5];
    const float* b1  = (const float*)d_in[6];
    const float* W2  = (const float*)d_in[7];
    const float* b2  = (const float*)d_in[8];
    const float* W3  = (const float*)d_in[9];
    const float* b3  = (const float*)d_in[10];
    const float* Wih = (const float*)d_in[11];
    const float* Whh = (const float*)d_in[12];
    const float* bih = (const float*)d_in[13];
    const float* bhh = (const float*)d_in[14];
    float* out_nf = (float*)d_out;
    float* out_ef = out_nf + (size_t)NN * HH;

    float *p_nf, *p_ef, *p_ein, *p_rel, *p_gi, *p_gh;
    cudaGetSymbolAddress((void**)&p_nf,  g_nf);
    cudaGetSymbolAddress((void**)&p_ef,  g_ef);
    cudaGetSymbolAddress((void**)&p_ein, g_ein);
    cudaGetSymbolAddress((void**)&p_rel, g_rel);
    cudaGetSymbolAddress((void**)&p_gi,  g_gi);
    cudaGetSymbolAddress((void**)&p_gh,  g_gh);

    const int TB = 256;
    k_zero_mask_deg<<<((size_t)RR * NN / 4 + TB - 1) / TB, TB>>>();
    k_build<<<(NE + TB - 1) / TB, TB>>>(src, dst, et);

    dim3 gE ((NE + 63) / 64, 2);   // E x 128 outputs
    dim3 gE3((NE + 63) / 64, 6);   // E x 384 outputs
    dim3 gN ((NN + 63) / 64, 2);   // N x 128 outputs
    size_t EH = (size_t)NE * HH;
    int gruBlocks = (int)((EH + TB - 1) / TB);

    for (int l = 0; l < 2; l++) {
        const float* nfi = (l == 0) ? nf0 : p_nf;
        const float* efi = (l == 0) ? ef0 : p_ef;
        float* nfo = (l == 0) ? p_nf : out_nf;
        float* efo = (l == 0) ? p_ef : out_ef;
        const float* W1l  = W1  + (size_t)l * HH * H3;
        const float* b1l  = b1  + (size_t)l * HH;
        const float* W2l  = W2  + (size_t)l * HH * H3;
        const float* b2l  = b2  + (size_t)l * HH;
        const float* W3l  = W3  + (size_t)l * HH * HH;
        const float* b3l  = b3  + (size_t)l * HH;
        const float* Wihl = Wih + (size_t)l * H3 * HH;
        const float* Whhl = Whh + (size_t)l * H3 * HH;
        const float* bihl = bih + (size_t)l * H3;
        const float* bhhl = bhh + (size_t)l * H3;

        k_zero_agg<<<((size_t)NN * HH + TB - 1) / TB, TB>>>();
        k_rel<<<RR, TB>>>(nfi);

        // msg = [rel(et), nf(src), ef] @ W1^T + b1  -> atomicAdd into g_agg[dst]
        k_gemm<<<gE, TB>>>(NE, H3, HH, p_rel, et, nfi, src, efi, nullptr,
                           W1l, b1l, nullptr, 1, dst);
        // e_in = [rel(et), nf(src), nf(dst)] @ W2^T + b2
        k_gemm<<<gE, TB>>>(NE, H3, HH, p_rel, et, nfi, src, nfi, dst,
                           W2l, b2l, p_ein, 0, nullptr);
        // gh = ef @ Whh^T + bhh   (shared by both GRU applications)
        k_gemm<<<gE3, TB>>>(NE, HH, H3, efi, nullptr, nullptr, nullptr, nullptr, nullptr,
                            Whhl, bhhl, p_gh, 0, nullptr);
        // gi = e_in @ Wih^T + bih
        k_gemm<<<gE3, TB>>>(NE, HH, H3, p_ein, nullptr, nullptr, nullptr, nullptr, nullptr,
                            Wihl, bihl, p_gi, 0, nullptr);
        // e_msg = GRU(e_in, ef)  -> overwrite g_ein
        k_gru<<<gruBlocks, TB>>>(efi, p_ein);
        // gi2 = e_msg @ Wih^T + bih
        k_gemm<<<gE3, TB>>>(NE, HH, H3, p_ein, nullptr, nullptr, nullptr, nullptr, nullptr,
                            Wihl, bihl, p_gi, 0, nullptr);
        // new_ef = GRU(e_msg, ef)
        k_gru<<<gruBlocks, TB>>>(efi, efo);
        // new_nf = rrelu(agg/deg + nf @ W3^T + b3)
        k_gemm<<<gN, TB>>>(NN, HH, HH, nfi, nullptr, nullptr, nullptr, nullptr, nullptr,
                           W3l, b3l, nfo, 2, nullptr);
    }
}

// round 2
// speedup vs baseline: 2.0093x; 2.0093x over previous
#include <cuda_runtime.h>
#include <math.h>

#define NN 30000
#define NE 300000
#define HH 128
#define H3 384
#define RR 200
#define RRELU_SLOPE 0.22916666666666666f

// ---------------- scratch (__device__ globals: alloc-free) ----------------
__device__ unsigned char g_mask[(size_t)RR * NN];      // 6 MB
__device__ float g_deg[NN];
__device__ float g_rel[RR * HH];
__device__ float g_agg[(size_t)NN * HH];
__device__ float g_nf [(size_t)NN * HH];
__device__ float g_ef [(size_t)NE * HH];
__device__ float g_ein[(size_t)NE * HH];
__device__ float g_gi [(size_t)NE * H3];
__device__ float g_gh [(size_t)NE * H3];

// ---------------- helpers ----------------
__device__ __forceinline__ unsigned f2tf(float x) {
    unsigned r;
    asm("cvt.rna.tf32.f32 %0, %1;" : "=r"(r) : "f"(x));
    return r;
}

#define MMA_TF32(c, a, b)                                                         \
    asm volatile(                                                                 \
        "mma.sync.aligned.m16n8k8.row.col.f32.tf32.tf32.f32 "                     \
        "{%0,%1,%2,%3}, {%4,%5,%6,%7}, {%8,%9}, {%0,%1,%2,%3};"                   \
        : "+f"(c[0]), "+f"(c[1]), "+f"(c[2]), "+f"(c[3])                          \
        : "r"(a[0]), "r"(a[1]), "r"(a[2]), "r"(a[3]), "r"(b[0]), "r"(b[1]))

// ---------------- zero kernels ----------------
__global__ void k_zero_mask_deg() {
    size_t i = (size_t)blockIdx.x * blockDim.x + threadIdx.x;
    const size_t W = (size_t)RR * NN / 4;
    if (i < W) ((unsigned int*)g_mask)[i] = 0u;
    if (i < NN) g_deg[i] = 0.0f;
}

__global__ void k_zero_agg() {
    size_t i = (size_t)blockIdx.x * blockDim.x + threadIdx.x;
    if (i < (size_t)NN * HH) g_agg[i] = 0.0f;
}

// ---------------- graph-structure build (once) ----------------
__global__ void k_build(const int* __restrict__ src, const int* __restrict__ dst,
                        const int* __restrict__ et) {
    int e = blockIdx.x * blockDim.x + threadIdx.x;
    if (e >= NE) return;
    int r = et[e];
    g_mask[(size_t)r * NN + src[e]] = 1;
    g_mask[(size_t)r * NN + dst[e]] = 1;
    atomicAdd(&g_deg[dst[e]], 1.0f);
}

// ---------------- rel_emb: masked mean of node feats per relation ----------
__global__ __launch_bounds__(256) void k_rel(const float* __restrict__ nf) {
    int r = blockIdx.x;
    int warp = threadIdx.x >> 5, lane = threadIdx.x & 31;
    const unsigned char* mrow = g_mask + (size_t)r * NN;
    float a0 = 0.f, a1 = 0.f, a2 = 0.f, a3 = 0.f;
    int cnt = 0;
    for (int base = warp * 32; base < NN; base += 256) {
        int n = base + lane;
        bool set = (n < NN) && mrow[n];
        unsigned ball = __ballot_sync(0xffffffffu, set);
        cnt += (int)set;
        while (ball) {
            int b = __ffs(ball) - 1;
            ball &= ball - 1;
            const float* row = nf + (size_t)(base + b) * HH;
            a0 += row[lane]; a1 += row[lane + 32];
            a2 += row[lane + 64]; a3 += row[lane + 96];
        }
    }
    __shared__ float ss[8][128];
    __shared__ int sc[8];
    #pragma unroll
    for (int off = 16; off; off >>= 1) cnt += __shfl_xor_sync(0xffffffffu, cnt, off);
    if (lane == 0) sc[warp] = cnt;
    ss[warp][lane] = a0; ss[warp][lane + 32] = a1;
    ss[warp][lane + 64] = a2; ss[warp][lane + 96] = a3;
    __syncthreads();
    if (threadIdx.x < 128) {
        float s = 0.f; int c = 0;
        #pragma unroll
        for (int w = 0; w < 8; w++) { s += ss[w][threadIdx.x]; c += sc[w]; }
        g_rel[r * HH + threadIdx.x] = (c > 0) ? s / (float)c : 0.0f;
    }
}

// ---------------- TF32 tensor-core fused gather-GEMM ------------------------
// C[M,Nout] = gatherX[M,K] @ W[Nout,K]^T + bias
// Tile: BM=64, BN=128, BK=32. 256 threads = 8 warps (2x4), warp tile 32x32.
// mode 0: plain store; mode 1: atomicAdd into g_agg[dst]; mode 2: node rrelu.
__global__ __launch_bounds__(256) void k_gemm_tc(
    int M, int K, int Nout,
    const float* __restrict__ s0, const int* __restrict__ i0,
    const float* __restrict__ s1, const int* __restrict__ i1,
    const float* __restrict__ s2, const int* __restrict__ i2,
    const float* __restrict__ W, const float* __restrict__ bias,
    float* __restrict__ out, int mode, const int* __restrict__ dstIdx)
{
    __shared__ unsigned As[32 * 65];    // As[k][m], stride 65 (==1 mod 32)
    __shared__ unsigned Bs[32 * 129];   // Bs[k][n], stride 129 (==1 mod 32)
    __shared__ const float* rowp[64][3];

    int tid = threadIdx.x;
    int m0 = blockIdx.x * 64, n0 = blockIdx.y * 128;

    if (tid < 64) {
        int e = m0 + tid;
        if (e > M - 1) e = M - 1;  // clamp; stores are guarded
        rowp[tid][0] = s0 + (size_t)(i0 ? i0[e] : e) * HH;
        rowp[tid][1] = s1 ? (s1 + (size_t)(i1 ? i1[e] : e) * HH) : s0;
        rowp[tid][2] = s2 ? (s2 + (size_t)(i2 ? i2[e] : e) * HH) : s0;
    }
    __syncthreads();

    int lane = tid & 31, wid = tid >> 5;
    int wm = wid >> 2, wn = wid & 3;          // warp 2x4 grid
    int g = lane >> 2, tg = lane & 3;

    float acc[2][4][4];
    #pragma unroll
    for (int a = 0; a < 2; a++)
        #pragma unroll
        for (int b = 0; b < 4; b++)
            #pragma unroll
            for (int c = 0; c < 4; c++) acc[a][b][c] = 0.0f;

    for (int kt = 0; kt < K; kt += 32) {
        int seg = kt >> 7, off0 = kt & 127;
        // A tile: 64 rows x 32 k, gathered. 512 float4 loads / 256 threads.
        #pragma unroll
        for (int i = 0; i < 2; i++) {
            int idx = tid + i * 256;
            int m = idx >> 3, q = idx & 7;
            float4 v = *(const float4*)(rowp[m][seg] + off0 + q * 4);
            As[(4 * q + 0) * 65 + m] = f2tf(v.x);
            As[(4 * q + 1) * 65 + m] = f2tf(v.y);
            As[(4 * q + 2) * 65 + m] = f2tf(v.z);
            As[(4 * q + 3) * 65 + m] = f2tf(v.w);
        }
        // B tile: 128 rows of W x 32 k. 1024 float4 loads / 256 threads.
        #pragma unroll
        for (int i = 0; i < 4; i++) {
            int idx = tid + i * 256;
            int n = idx >> 3, q = idx & 7;
            float4 v = *(const float4*)(W + (size_t)(n0 + n) * K + kt + q * 4);
            Bs[(4 * q + 0) * 129 + n] = f2tf(v.x);
            Bs[(4 * q + 1) * 129 + n] = f2tf(v.y);
            Bs[(4 * q + 2) * 129 + n] = f2tf(v.z);
            Bs[(4 * q + 3) * 129 + n] = f2tf(v.w);
        }
        __syncthreads();

        #pragma unroll
        for (int ks = 0; ks < 32; ks += 8) {
            unsigned afr[2][4];
            #pragma unroll
            for (int mt = 0; mt < 2; mt++) {
                int mb = wm * 32 + mt * 16;
                afr[mt][0] = As[(ks + tg) * 65 + mb + g];
                afr[mt][1] = As[(ks + tg) * 65 + mb + g + 8];
                afr[mt][2] = As[(ks + tg + 4) * 65 + mb + g];
                afr[mt][3] = As[(ks + tg + 4) * 65 + mb + g + 8];
            }
            unsigned bfr[4][2];
            #pragma unroll
            for (int nt = 0; nt < 4; nt++) {
                int nb = wn * 32 + nt * 8;
                bfr[nt][0] = Bs[(ks + tg) * 129 + nb + g];
                bfr[nt][1] = Bs[(ks + tg + 4) * 129 + nb + g];
            }
            #pragma unroll
            for (int mt = 0; mt < 2; mt++)
                #pragma unroll
                for (int nt = 0; nt < 4; nt++)
                    MMA_TF32(acc[mt][nt], afr[mt], bfr[nt]);
        }
        __syncthreads();
    }

    // epilogue: each thread owns (r, c), (r, c+1), (r+8, c), (r+8, c+1) per tile
    #pragma unroll
    for (int mt = 0; mt < 2; mt++) {
        #pragma unroll
        for (int half = 0; half < 2; half++) {
            int mm = m0 + wm * 32 + mt * 16 + g + half * 8;
            if (mm >= M) continue;
            #pragma unroll
            for (int nt = 0; nt < 4; nt++) {
                int nn = n0 + wn * 32 + nt * 8 + 2 * tg;
                float v0 = acc[mt][nt][half * 2 + 0] + bias[nn];
                float v1 = acc[mt][nt][half * 2 + 1] + bias[nn + 1];
                if (mode == 0) {
                    out[(size_t)mm * Nout + nn]     = v0;
                    out[(size_t)mm * Nout + nn + 1] = v1;
                } else if (mode == 1) {
                    atomicAdd(&g_agg[(size_t)dstIdx[mm] * HH + nn], v0);
                    atomicAdd(&g_agg[(size_t)dstIdx[mm] * HH + nn + 1], v1);
                } else {
                    float inv = 1.0f / fmaxf(g_deg[mm], 1.0f);
                    float p0 = v0 + g_agg[(size_t)mm * HH + nn] * inv;
                    float p1 = v1 + g_agg[(size_t)mm * HH + nn + 1] * inv;
                    out[(size_t)mm * HH + nn]     = (p0 >= 0.f) ? p0 : RRELU_SLOPE * p0;
                    out[(size_t)mm * HH + nn + 1] = (p1 >= 0.f) ? p1 : RRELU_SLOPE * p1;
                }
            }
        }
    }
}

// ---------------- GRU elementwise combine (float4) --------------------------
__global__ void k_gru(const float* __restrict__ ef_in, float* __restrict__ out) {
    size_t idx = (size_t)blockIdx.x * blockDim.x + threadIdx.x;
    if (idx >= (size_t)NE * 32) return;
    size_t e = idx >> 5;
    int h = (int)(idx & 31) * 4;
    const float* gi = g_gi + e * H3;
    const float* gh = g_gh + e * H3;
    float4 ir = *(const float4*)(gi + h);
    float4 iz = *(const float4*)(gi + 128 + h);
    float4 in_ = *(const float4*)(gi + 256 + h);
    float4 hr = *(const float4*)(gh + h);
    float4 hz = *(const float4*)(gh + 128 + h);
    float4 hn = *(const float4*)(gh + 256 + h);
    float4 hv = *(const float4*)(ef_in + e * HH + h);
    float4 o;
    {
        float r = 1.0f / (1.0f + expf(-(ir.x + hr.x)));
        float z = 1.0f / (1.0f + expf(-(iz.x + hz.x)));
        float n = tanhf(in_.x + r * hn.x);
        o.x = (1.0f - z) * n + z * hv.x;
    }
    {
        float r = 1.0f / (1.0f + expf(-(ir.y + hr.y)));
        float z = 1.0f / (1.0f + expf(-(iz.y + hz.y)));
        float n = tanhf(in_.y + r * hn.y);
        o.y = (1.0f - z) * n + z * hv.y;
    }
    {
        float r = 1.0f / (1.0f + expf(-(ir.z + hr.z)));
        float z = 1.0f / (1.0f + expf(-(iz.z + hz.z)));
        float n = tanhf(in_.z + r * hn.z);
        o.z = (1.0f - z) * n + z * hv.z;
    }
    {
        float r = 1.0f / (1.0f + expf(-(ir.w + hr.w)));
        float z = 1.0f / (1.0f + expf(-(iz.w + hz.w)));
        float n = tanhf(in_.w + r * hn.w);
        o.w = (1.0f - z) * n + z * hv.w;
    }
    *(float4*)(out + e * HH + h) = o;
}

// ---------------- launch ----------------------------------------------------
extern "C" void kernel_launch(void* const* d_in, const int* in_sizes, int n_in,
                              void* d_out, int out_size) {
    (void)in_sizes; (void)n_in; (void)out_size;
    const float* nf0 = (const float*)d_in[0];
    const float* ef0 = (const float*)d_in[1];
    const int* src = (const int*)d_in[2];
    const int* dst = (const int*)d_in[3];
    const int* et  = (const int*)d_in[4];
    const float* W1  = (const float*)d_in[5];
    const float* b1  = (const float*)d_in[6];
    const float* W2  = (const float*)d_in[7];
    const float* b2  = (const float*)d_in[8];
    const float* W3  = (const float*)d_in[9];
    const float* b3  = (const float*)d_in[10];
    const float* Wih = (const float*)d_in[11];
    const float* Whh = (const float*)d_in[12];
    const float* bih = (const float*)d_in[13];
    const float* bhh = (const float*)d_in[14];
    float* out_nf = (float*)d_out;
    float* out_ef = out_nf + (size_t)NN * HH;

    float *p_nf, *p_ef, *p_ein, *p_rel, *p_gi, *p_gh;
    cudaGetSymbolAddress((void**)&p_nf,  g_nf);
    cudaGetSymbolAddress((void**)&p_ef,  g_ef);
    cudaGetSymbolAddress((void**)&p_ein, g_ein);
    cudaGetSymbolAddress((void**)&p_rel, g_rel);
    cudaGetSymbolAddress((void**)&p_gi,  g_gi);
    cudaGetSymbolAddress((void**)&p_gh,  g_gh);

    const int TB = 256;
    k_zero_mask_deg<<<((size_t)RR * NN / 4 + TB - 1) / TB, TB>>>();
    k_build<<<(NE + TB - 1) / TB, TB>>>(src, dst, et);

    dim3 gE ((NE + 63) / 64, 1);   // E x 128 outputs
    dim3 gE3((NE + 63) / 64, 3);   // E x 384 outputs
    dim3 gN ((NN + 63) / 64, 1);   // N x 128 outputs
    int gruBlocks = (int)(((size_t)NE * 32 + TB - 1) / TB);

    for (int l = 0; l < 2; l++) {
        const float* nfi = (l == 0) ? nf0 : p_nf;
        const float* efi = (l == 0) ? ef0 : p_ef;
        float* nfo = (l == 0) ? p_nf : out_nf;
        float* efo = (l == 0) ? p_ef : out_ef;
        const float* W1l  = W1  + (size_t)l * HH * H3;
        const float* b1l  = b1  + (size_t)l * HH;
        const float* W2l  = W2  + (size_t)l * HH * H3;
        const float* b2l  = b2  + (size_t)l * HH;
        const float* W3l  = W3  + (size_t)l * HH * HH;
        const float* b3l  = b3  + (size_t)l * HH;
        const float* Wihl = Wih + (size_t)l * H3 * HH;
        const float* Whhl = Whh + (size_t)l * H3 * HH;
        const float* bihl = bih + (size_t)l * H3;
        const float* bhhl = bhh + (size_t)l * H3;

        k_zero_agg<<<((size_t)NN * HH + TB - 1) / TB, TB>>>();
        k_rel<<<RR, TB>>>(nfi);

        // msg = [rel(et), nf(src), ef] @ W1^T + b1  -> atomicAdd into g_agg[dst]
        k_gemm_tc<<<gE, TB>>>(NE, H3, HH, p_rel, et, nfi, src, efi, nullptr,
                              W1l, b1l, nullptr, 1, dst);
        // e_in = [rel(et), nf(src), nf(dst)] @ W2^T + b2
        k_gemm_tc<<<gE, TB>>>(NE, H3, HH, p_rel, et, nfi, src, nfi, dst,
                              W2l, b2l, p_ein, 0, nullptr);
        // gh = ef @ Whh^T + bhh   (shared by both GRU applications)
        k_gemm_tc<<<gE3, TB>>>(NE, HH, H3, efi, nullptr, nullptr, nullptr, nullptr, nullptr,
                               Whhl, bhhl, p_gh, 0, nullptr);
        // gi = e_in @ Wih^T + bih
        k_gemm_tc<<<gE3, TB>>>(NE, HH, H3, p_ein, nullptr, nullptr, nullptr, nullptr, nullptr,
                               Wihl, bihl, p_gi, 0, nullptr);
        // e_msg = GRU(e_in, ef)  -> overwrite g_ein
        k_gru<<<gruBlocks, TB>>>(efi, p_ein);
        // gi2 = e_msg @ Wih^T + bih
        k_gemm_tc<<<gE3, TB>>>(NE, HH, H3, p_ein, nullptr, nullptr, nullptr, nullptr, nullptr,
                               Wihl, bihl, p_gi, 0, nullptr);
        // new_ef = GRU(e_msg, ef)
        k_gru<<<gruBlocks, TB>>>(efi, efo);
        // new_nf = rrelu(agg/deg + nf @ W3^T + b3)
        k_gemm_tc<<<gN, TB>>>(NN, HH, HH, nfi, nullptr, nullptr, nullptr, nullptr, nullptr,
                              W3l, b3l, nfo, 2, nullptr);
    }
}

// round 3
// speedup vs baseline: 3.3069x; 1.6458x over previous
#include <cuda_runtime.h>
#include <math.h>

#define NN 30000
#define NE 300000
#define HH 128
#define H3 384
#define RR 200
#define RRELU_SLOPE 0.22916666666666666f

// ---------------- scratch ----------------
__device__ unsigned char g_mask[(size_t)RR * NN];
__device__ float g_deg[NN];
__device__ float g_rel[RR * HH];
__device__ float g_relsum[RR * HH];
__device__ int   g_relcnt[RR];
__device__ float g_agg[(size_t)NN * HH];
__device__ float g_nf [(size_t)NN * HH];
__device__ float g_ef [(size_t)NE * HH];
__device__ float g_ein[(size_t)NE * HH];
__device__ float g_emsg[(size_t)NE * HH];
__device__ float g_Wp[2 * 512 * 256];   // gate-interleaved GRU weights
__device__ float g_bp[2 * 512];

// ---------------- helpers ----------------
__device__ __forceinline__ unsigned f2tf(float x) {
    unsigned r;
    asm("cvt.rna.tf32.f32 %0, %1;" : "=r"(r) : "f"(x));
    return r;
}
__device__ __forceinline__ float sig_f(float x) { return 1.0f / (1.0f + __expf(-x)); }
__device__ __forceinline__ float tanh_f(float x) { return 2.0f / (1.0f + __expf(-2.0f * x)) - 1.0f; }

#define MMA_TF32(c, a, b)                                                         \
    asm volatile(                                                                 \
        "mma.sync.aligned.m16n8k8.row.col.f32.tf32.tf32.f32 "                     \
        "{%0,%1,%2,%3}, {%4,%5,%6,%7}, {%8,%9}, {%0,%1,%2,%3};"                   \
        : "+f"(c[0]), "+f"(c[1]), "+f"(c[2]), "+f"(c[3])                          \
        : "r"(a[0]), "r"(a[1]), "r"(a[2]), "r"(a[3]), "r"(b[0]), "r"(b[1]))

// ---------------- zero / build ----------------
__global__ void k_zero_mask_deg() {
    size_t i = (size_t)blockIdx.x * blockDim.x + threadIdx.x;
    const size_t W = (size_t)RR * NN / 4;
    if (i < W) ((unsigned int*)g_mask)[i] = 0u;
    if (i < NN) g_deg[i] = 0.0f;
}

__global__ void k_zero2() {   // per-layer: agg + relsum + relcnt
    size_t i = (size_t)blockIdx.x * blockDim.x + threadIdx.x;
    if (i < (size_t)NN * HH) g_agg[i] = 0.0f;
    if (i < RR * HH) g_relsum[i] = 0.0f;
    if (i < RR) g_relcnt[i] = 0;
}

__global__ void k_build(const int* __restrict__ src, const int* __restrict__ dst,
                        const int* __restrict__ et) {
    int e = blockIdx.x * blockDim.x + threadIdx.x;
    if (e >= NE) return;
    int r = et[e];
    g_mask[(size_t)r * NN + src[e]] = 1;
    g_mask[(size_t)r * NN + dst[e]] = 1;
    atomicAdd(&g_deg[dst[e]], 1.0f);
}

// ---------------- GRU weight packing --------------------------------------
// W'[l][4h+gate][k], k<128 from Wih, k>=128 from Whh.
// gate0: r-sum row (Wih[h], Whh[h]); gate1: z-sum (rows 128+h)
// gate2: (Wih[256+h], 0); gate3: (0, Whh[256+h])
__global__ void k_pack(const float* __restrict__ Wih, const float* __restrict__ Whh,
                       const float* __restrict__ bih, const float* __restrict__ bhh) {
    int idx = blockIdx.x * blockDim.x + threadIdx.x;
    if (idx >= 2 * 512 * 256) return;
    int l = idx >> 17;
    int rp = (idx >> 8) & 511;
    int k = idx & 255;
    int h = rp >> 2, gate = rp & 3;
    const float* wi = Wih + (size_t)l * H3 * HH;
    const float* wh = Whh + (size_t)l * H3 * HH;
    float v;
    if (gate == 0) v = (k < 128) ? wi[h * HH + k] : wh[h * HH + k - 128];
    else if (gate == 1) v = (k < 128) ? wi[(128 + h) * HH + k] : wh[(128 + h) * HH + k - 128];
    else if (gate == 2) v = (k < 128) ? wi[(256 + h) * HH + k] : 0.0f;
    else v = (k < 128) ? 0.0f : wh[(256 + h) * HH + k - 128];
    g_Wp[idx] = v;
    if (k == 0) {
        const float* bi = bih + l * H3;
        const float* bh = bhh + l * H3;
        float b;
        if (gate == 0) b = bi[h] + bh[h];
        else if (gate == 1) b = bi[128 + h] + bh[128 + h];
        else if (gate == 2) b = bi[256 + h];
        else b = bh[256 + h];
        g_bp[l * 512 + rp] = b;
    }
}

// ---------------- rel_emb (split 4-way) ------------------------------------
__global__ __launch_bounds__(256) void k_rel_part(const float* __restrict__ nf) {
    int r = blockIdx.x;
    int nbeg = blockIdx.y * 7500;
    int nend = nbeg + 7500; if (nend > NN) nend = NN;
    int warp = threadIdx.x >> 5, lane = threadIdx.x & 31;
    const unsigned char* mrow = g_mask + (size_t)r * NN;
    float a0 = 0.f, a1 = 0.f, a2 = 0.f, a3 = 0.f;
    int cnt = 0;
    for (int base = nbeg + warp * 32; base < nend; base += 256) {
        int n = base + lane;
        bool set = (n < nend) && mrow[n];
        unsigned ball = __ballot_sync(0xffffffffu, set);
        cnt += (int)set;
        while (ball) {
            int b = __ffs(ball) - 1;
            ball &= ball - 1;
            const float* row = nf + (size_t)(base + b) * HH;
            a0 += row[lane]; a1 += row[lane + 32];
            a2 += row[lane + 64]; a3 += row[lane + 96];
        }
    }
    __shared__ float ss[8][128];
    __shared__ int sc[8];
    #pragma unroll
    for (int off = 16; off; off >>= 1) cnt += __shfl_xor_sync(0xffffffffu, cnt, off);
    if (lane == 0) sc[warp] = cnt;
    ss[warp][lane] = a0; ss[warp][lane + 32] = a1;
    ss[warp][lane + 64] = a2; ss[warp][lane + 96] = a3;
    __syncthreads();
    if (threadIdx.x < 128) {
        float s = 0.f;
        #pragma unroll
        for (int w = 0; w < 8; w++) s += ss[w][threadIdx.x];
        atomicAdd(&g_relsum[r * HH + threadIdx.x], s);
    }
    if (threadIdx.x == 128) {
        int c = 0;
        #pragma unroll
        for (int w = 0; w < 8; w++) c += sc[w];
        atomicAdd(&g_relcnt[r], c);
    }
}

__global__ void k_rel_fin() {
    int idx = blockIdx.x * blockDim.x + threadIdx.x;
    if (idx >= RR * HH) return;
    int c = g_relcnt[idx >> 7];
    g_rel[idx] = (c > 0) ? g_relsum[idx] / (float)c : 0.0f;
}

// ---------------- TF32 TC gather-GEMM v3 -----------------------------------
// BM=128, BN=128, BK=32; 256 thr = 8 warps (4m x 2n); warp 32m x 64n.
// smem row-stride 40 (conflict-free frags); k-lane permutation: MMA k-lane tg
// covers physical k {2tg, 2tg+1} (consistent A&B -> result unchanged).
// mode 0: store; 1: atomicAdd g_agg[dst]; 2: node rrelu; 3: fused GRU.
__global__ __launch_bounds__(256, 2) void k_gemm_v3(
    int M, int K, int Nout,
    const float* __restrict__ s0, const int* __restrict__ i0,
    const float* __restrict__ s1, const int* __restrict__ i1,
    const float* __restrict__ s2, const int* __restrict__ i2,
    const float* __restrict__ W, const float* __restrict__ bias,
    float* __restrict__ out, int mode, const int* __restrict__ dstIdx)
{
    __shared__ unsigned As[128 * 40];
    __shared__ unsigned Bs[128 * 40];
    __shared__ const float* rowp[128][3];

    int tid = threadIdx.x;
    int m0 = blockIdx.x * 128, n0 = blockIdx.y * 128;

    if (tid < 128) {
        int e = m0 + tid; if (e > M - 1) e = M - 1;
        rowp[tid][0] = s0 + (size_t)(i0 ? i0[e] : e) * HH;
        rowp[tid][1] = s1 ? (s1 + (size_t)(i1 ? i1[e] : e) * HH) : s0;
        rowp[tid][2] = s2 ? (s2 + (size_t)(i2 ? i2[e] : e) * HH) : s0;
    }
    __syncthreads();

    int lane = tid & 31, wid = tid >> 5;
    int wm = wid >> 1, wn = wid & 1;
    int g = lane >> 2, tg = lane & 3;
    int am = tid >> 3, aq = tid & 7;   // loader row/quad

    float acc[2][8][4];
    #pragma unroll
    for (int a = 0; a < 2; a++)
        #pragma unroll
        for (int b = 0; b < 8; b++)
            #pragma unroll
            for (int c = 0; c < 4; c++) acc[a][b][c] = 0.0f;

    float4 pa[4], pb[4];
    // prefetch kt=0
    #pragma unroll
    for (int i = 0; i < 4; i++) {
        pa[i] = *(const float4*)(rowp[am + 32 * i][0] + aq * 4);
        pb[i] = *(const float4*)(W + (size_t)(n0 + am + 32 * i) * K + aq * 4);
    }

    for (int kt = 0; kt < K; kt += 32) {
        // commit prefetched tile to smem (tf32-rounded)
        #pragma unroll
        for (int i = 0; i < 4; i++) {
            int r = am + 32 * i;
            uint4 ta = { f2tf(pa[i].x), f2tf(pa[i].y), f2tf(pa[i].z), f2tf(pa[i].w) };
            uint4 tb = { f2tf(pb[i].x), f2tf(pb[i].y), f2tf(pb[i].z), f2tf(pb[i].w) };
            *(uint4*)&As[r * 40 + aq * 4] = ta;
            *(uint4*)&Bs[r * 40 + aq * 4] = tb;
        }
        __syncthreads();
        // prefetch next
        int kt2 = kt + 32;
        if (kt2 < K) {
            int seg = kt2 >> 7, off = (kt2 & 127) + aq * 4;
            #pragma unroll
            for (int i = 0; i < 4; i++) {
                pa[i] = *(const float4*)(rowp[am + 32 * i][seg] + off);
                pb[i] = *(const float4*)(W + (size_t)(n0 + am + 32 * i) * K + kt2 + aq * 4);
            }
        }
        // MMAs
        #pragma unroll
        for (int ks = 0; ks < 32; ks += 8) {
            unsigned afr[2][4];
            #pragma unroll
            for (int mt = 0; mt < 2; mt++) {
                int rA = wm * 32 + mt * 16 + g;
                uint2 lo = *(const uint2*)&As[rA * 40 + ks + 2 * tg];
                uint2 hi = *(const uint2*)&As[(rA + 8) * 40 + ks + 2 * tg];
                afr[mt][0] = lo.x; afr[mt][1] = hi.x; afr[mt][2] = lo.y; afr[mt][3] = hi.y;
            }
            unsigned bfr[8][2];
            #pragma unroll
            for (int nt = 0; nt < 8; nt++) {
                int rB = wn * 64 + nt * 8 + g;
                uint2 v = *(const uint2*)&Bs[rB * 40 + ks + 2 * tg];
                bfr[nt][0] = v.x; bfr[nt][1] = v.y;
            }
            #pragma unroll
            for (int mt = 0; mt < 2; mt++)
                #pragma unroll
                for (int nt = 0; nt < 8; nt++)
                    MMA_TF32(acc[mt][nt], afr[mt], bfr[nt]);
        }
        __syncthreads();
    }

    // ---------------- epilogue ----------------
    #pragma unroll
    for (int mt = 0; mt < 2; mt++) {
        #pragma unroll
        for (int half = 0; half < 2; half++) {
            int mm = m0 + wm * 32 + mt * 16 + g + half * 8;
            bool okm = (mm < M);
            int mr = wm * 32 + mt * 16 + g + half * 8;   // row within block
            #pragma unroll
            for (int nt = 0; nt < 8; nt++) {
                int nn = n0 + wn * 64 + nt * 8 + 2 * tg;
                float v0 = acc[mt][nt][half * 2 + 0] + bias[nn];
                float v1 = acc[mt][nt][half * 2 + 1] + bias[nn + 1];
                if (mode == 3) {
                    // gate interleave: even tg lane = (s_r, s_z); odd = (i_n, h_n)
                    float sg0 = sig_f(v0), sg1 = sig_f(v1);
                    float rr = __shfl_xor_sync(0xffffffffu, sg0, 1);
                    float zz = __shfl_xor_sync(0xffffffffu, sg1, 1);
                    if ((tg & 1) && okm) {
                        float nval = tanh_f(v0 + rr * v1);
                        int h0 = nn >> 2;
                        float hv = rowp[mr][1][h0];
                        out[(size_t)mm * HH + h0] = (1.0f - zz) * nval + zz * hv;
                    }
                } else if (mode == 0) {
                    if (okm) { float2 o = { v0, v1 }; *(float2*)&out[(size_t)mm * Nout + nn] = o; }
                } else if (mode == 1) {
                    if (okm) {
                        atomicAdd(&g_agg[(size_t)dstIdx[mm] * HH + nn], v0);
                        atomicAdd(&g_agg[(size_t)dstIdx[mm] * HH + nn + 1], v1);
                    }
                } else {
                    if (okm) {
                        float inv = 1.0f / fmaxf(g_deg[mm], 1.0f);
                        float p0 = v0 + g_agg[(size_t)mm * HH + nn] * inv;
                        float p1 = v1 + g_agg[(size_t)mm * HH + nn + 1] * inv;
                        float2 o = { (p0 >= 0.f) ? p0 : RRELU_SLOPE * p0,
                                     (p1 >= 0.f) ? p1 : RRELU_SLOPE * p1 };
                        *(float2*)&out[(size_t)mm * HH + nn] = o;
                    }
                }
            }
        }
    }
}

// ---------------- launch ----------------------------------------------------
extern "C" void kernel_launch(void* const* d_in, const int* in_sizes, int n_in,
                              void* d_out, int out_size) {
    (void)in_sizes; (void)n_in; (void)out_size;
    const float* nf0 = (const float*)d_in[0];
    const float* ef0 = (const float*)d_in[1];
    const int* src = (const int*)d_in[2];
    const int* dst = (const int*)d_in[3];
    const int* et  = (const int*)d_in[4];
    const float* W1  = (const float*)d_in[5];
    const float* b1  = (const float*)d_in[6];
    const float* W2  = (const float*)d_in[7];
    const float* b2  = (const float*)d_in[8];
    const float* W3  = (const float*)d_in[9];
    const float* b3  = (const float*)d_in[10];
    const float* Wih = (const float*)d_in[11];
    const float* Whh = (const float*)d_in[12];
    const float* bih = (const float*)d_in[13];
    const float* bhh = (const float*)d_in[14];
    float* out_nf = (float*)d_out;
    float* out_ef = out_nf + (size_t)NN * HH;

    float *p_nf, *p_ef, *p_ein, *p_emsg, *p_rel, *p_Wp, *p_bp;
    cudaGetSymbolAddress((void**)&p_nf,   g_nf);
    cudaGetSymbolAddress((void**)&p_ef,   g_ef);
    cudaGetSymbolAddress((void**)&p_ein,  g_ein);
    cudaGetSymbolAddress((void**)&p_emsg, g_emsg);
    cudaGetSymbolAddress((void**)&p_rel,  g_rel);
    cudaGetSymbolAddress((void**)&p_Wp,   g_Wp);
    cudaGetSymbolAddress((void**)&p_bp,   g_bp);

    const int TB = 256;
    k_zero_mask_deg<<<((size_t)RR * NN / 4 + TB - 1) / TB, TB>>>();
    k_build<<<(NE + TB - 1) / TB, TB>>>(src, dst, et);
    k_pack<<<(2 * 512 * 256 + TB - 1) / TB, TB>>>(Wih, Whh, bih, bhh);

    dim3 gE ((NE + 127) / 128, 1);   // E x 128
    dim3 gF ((NE + 127) / 128, 4);   // E x 512 (fused GRU)
    dim3 gN ((NN + 127) / 128, 1);   // N x 128
    dim3 gR (RR, 4);

    for (int l = 0; l < 2; l++) {
        const float* nfi = (l == 0) ? nf0 : p_nf;
        const float* efi = (l == 0) ? ef0 : p_ef;
        float* nfo = (l == 0) ? p_nf : out_nf;
        float* efo = (l == 0) ? p_ef : out_ef;
        const float* W1l  = W1  + (size_t)l * HH * H3;
        const float* b1l  = b1  + (size_t)l * HH;
        const float* W2l  = W2  + (size_t)l * HH * H3;
        const float* b2l  = b2  + (size_t)l * HH;
        const float* W3l  = W3  + (size_t)l * HH * HH;
        const float* b3l  = b3  + (size_t)l * HH;
        const float* Wpl  = p_Wp + (size_t)l * 512 * 256;
        const float* bpl  = p_bp + (size_t)l * 512;

        k_zero2<<<((size_t)NN * HH + TB - 1) / TB, TB>>>();
        k_rel_part<<<gR, TB>>>(nfi);
        k_rel_fin<<<(RR * HH + TB - 1) / TB, TB>>>();

        // msg GEMM -> atomic agg
        k_gemm_v3<<<gE, TB>>>(NE, H3, HH, p_rel, et, nfi, src, efi, nullptr,
                              W1l, b1l, nullptr, 1, dst);
        // e_in GEMM
        k_gemm_v3<<<gE, TB>>>(NE, H3, HH, p_rel, et, nfi, src, nfi, dst,
                              W2l, b2l, p_ein, 0, nullptr);
        // fused GRU #1: e_msg = GRU(e_in, ef)
        k_gemm_v3<<<gF, TB>>>(NE, 256, 512, p_ein, nullptr, efi, nullptr, nullptr, nullptr,
                              Wpl, bpl, p_emsg, 3, nullptr);
        // fused GRU #2: new_ef = GRU(e_msg, ef)
        k_gemm_v3<<<gF, TB>>>(NE, 256, 512, p_emsg, nullptr, efi, nullptr, nullptr, nullptr,
                              Wpl, bpl, efo, 3, nullptr);
        // node update
        k_gemm_v3<<<gN, TB>>>(NN, HH, HH, nfi, nullptr, nullptr, nullptr, nullptr, nullptr,
                              W3l, b3l, nfo, 2, nullptr);
    }
}